// round 13
// baseline (speedup 1.0000x reference)
#include <cuda_runtime.h>
#include <math.h>

#define N_NODES 8192
#define F_IN    256
#define F_OUT   64
#define ALPHA   0.2f
#define EMAX    128            // per-row edge cap (mean ~33, max ~58 @ p=0.004)
#define GEMM_BLOCKS 256        // 32-row x 64-col tiles
#define SCAN_BLOCKS 444        // ~3 blocks/SM (66KB dyn smem each)
#define STAGE_BYTES 4096       // 1024 cols per pipeline stage
#define DSM_BYTES   (8 * 2 * STAGE_BYTES + 8 * 16)   // 65,664

// Scratch (__device__ globals; no allocation allowed) --------------------
__device__ __align__(16) float g_Wh[N_NODES * F_OUT];   // 2 MB (L2-resident)
__device__ float g_wh1[N_NODES];
__device__ float g_wh2[N_NODES];
__device__ float g_Sall[F_OUT];
__device__ int            g_ecnt[N_NODES];
__device__ unsigned short g_eidx[N_NODES * EMAX];       // 2 MB compact lists
__device__ int g_next;                                  // row steal counter

__global__ void k_init() { g_next = 0; }

__device__ __forceinline__ int warp_steal(int l) {
    int r = 0;
    if (l == 0) r = atomicAdd(&g_next, 1);
    return __shfl_sync(0xFFFFFFFFu, r, 0);
}

__device__ __forceinline__ void tma_issue(int l, unsigned dst, unsigned mbar,
                                          const float* src) {
    if (l == 0) {
        asm volatile("mbarrier.arrive.expect_tx.shared.b64 _, [%0], %1;"
                     :: "r"(mbar), "r"(STAGE_BYTES) : "memory");
        asm volatile("cp.async.bulk.shared::cta.global.mbarrier::complete_tx::bytes "
                     "[%0], [%1], %2, [%3];"
                     :: "r"(dst), "l"(src), "r"(STAGE_BYTES), "r"(mbar) : "memory");
    }
}

__device__ __forceinline__ void mbar_wait(unsigned mbar, int parity) {
    asm volatile(
        "{\n\t.reg .pred P1;\n"
        "W_%=:\n\t"
        "mbarrier.try_wait.parity.acquire.cta.shared::cta.b64 P1, [%0], %1;\n\t"
        "@P1 bra D_%=;\n\t"
        "bra W_%=;\n"
        "D_%=:\n\t}"
        :: "r"(mbar), "r"(parity) : "memory");
}

// ========================================================================
// K1: heterogeneous, 66KB dynamic smem, <=84 regs.
//   blocks [0,256): GEMM Wh=h@W (32x64 tile, 2x4 micro) + wh1/wh2
//     epilogue — then FALL THROUGH to the scan steal pool.
//   blocks [256,700): straight to the pool.
// Scan pool: ONE WARP = ONE ROW (lane-0 atomic steal; row content is
// executor-independent -> deterministic). Warp walks its row in 8 stages
// of 4KB via per-warp TMA double buffer (2 bufs + 2 mbarriers): stage k+1
// is in flight while stage k is processed from smem -> loads never pause
// during the process window. Compact edge list + total count per row
// (R9 gather format), zero block barriers in the scan.
// ========================================================================
extern __shared__ __align__(16) char dsm[];

__global__ __launch_bounds__(256, 3) void k_fused(const float* __restrict__ h,
                                                  const float* __restrict__ W,
                                                  const float* __restrict__ a,
                                                  const float* __restrict__ adj) {
    const int t = threadIdx.x;
    const int w = t >> 5, l = t & 31;

    if (blockIdx.x < GEMM_BLOCKS) {
        // ----------------- GEMM branch (2x4 micro) -----------------
        float* hs = (float*)dsm;                 // [32][68] = 8.7 KB
        float* Ws = (float*)(dsm + 32 * 68 * 4); // [64][64] = 16.4 KB
        const int tx = t & 15;
        const int ty = t >> 4;
        const int u0 = blockIdx.x * 32;

        float acc[2][4] = {};

        for (int kc = 0; kc < 4; kc++) {
            #pragma unroll
            for (int i = 0; i < 2; i++) {
                int idx4 = i * 256 + t;
                int r = idx4 >> 4, k4 = idx4 & 15;
                *(float4*)&hs[r * 68 + k4 * 4] =
                    *(const float4*)&h[(size_t)(u0 + r) * F_IN + kc * 64 + k4 * 4];
            }
            #pragma unroll
            for (int i = 0; i < 4; i++) {
                int idx4 = i * 256 + t;
                int k = idx4 >> 4, c4 = idx4 & 15;
                *(float4*)&Ws[k * 64 + c4 * 4] =
                    *(const float4*)&W[(size_t)(kc * 64 + k) * F_OUT + c4 * 4];
            }
            __syncthreads();

            #pragma unroll
            for (int kk = 0; kk < 64; kk += 4) {
                float4 wv[4], hv[2];
                #pragma unroll
                for (int q = 0; q < 4; q++)
                    wv[q] = *(const float4*)&Ws[(kk + q) * 64 + tx * 4];
                #pragma unroll
                for (int r = 0; r < 2; r++)
                    hv[r] = *(const float4*)&hs[(ty * 2 + r) * 68 + kk];
                #pragma unroll
                for (int r = 0; r < 2; r++) {
                    acc[r][0] += hv[r].x * wv[0].x + hv[r].y * wv[1].x + hv[r].z * wv[2].x + hv[r].w * wv[3].x;
                    acc[r][1] += hv[r].x * wv[0].y + hv[r].y * wv[1].y + hv[r].z * wv[2].y + hv[r].w * wv[3].y;
                    acc[r][2] += hv[r].x * wv[0].z + hv[r].y * wv[1].z + hv[r].z * wv[2].z + hv[r].w * wv[3].z;
                    acc[r][3] += hv[r].x * wv[0].w + hv[r].y * wv[1].w + hv[r].z * wv[2].w + hv[r].w * wv[3].w;
                }
            }
            __syncthreads();
        }

        float4 a1v = *(const float4*)&a[F_OUT + tx * 4];  // source/row term a[f_out:]
        float4 a2v = *(const float4*)&a[tx * 4];          // dest/col  term a[:f_out]
        #pragma unroll
        for (int r = 0; r < 2; r++) {
            int row = u0 + ty * 2 + r;
            *(float4*)&g_Wh[(size_t)row * F_OUT + tx * 4] =
                make_float4(acc[r][0], acc[r][1], acc[r][2], acc[r][3]);
            float s1 = acc[r][0] * a1v.x + acc[r][1] * a1v.y + acc[r][2] * a1v.z + acc[r][3] * a1v.w;
            float s2 = acc[r][0] * a2v.x + acc[r][1] * a2v.y + acc[r][2] * a2v.z + acc[r][3] * a2v.w;
            #pragma unroll
            for (int off = 8; off; off >>= 1) {
                s1 += __shfl_xor_sync(0xFFFFFFFFu, s1, off);
                s2 += __shfl_xor_sync(0xFFFFFFFFu, s2, off);
            }
            if (tx == 0) { g_wh1[row] = s1; g_wh2[row] = s2; }
        }
        __syncthreads();   // smem handoff: GEMM tiles dead, scan buffers live
    }

    // ----------------- TMA scan pool (warp-autonomous) -----------------
    unsigned buf0 = (unsigned)__cvta_generic_to_shared(dsm + w * 2 * STAGE_BYTES);
    unsigned buf1 = buf0 + STAGE_BYTES;
    unsigned mb0  = (unsigned)__cvta_generic_to_shared(dsm + 16 * STAGE_BYTES + w * 16);
    unsigned mb1  = mb0 + 8;

    if (l == 0) {
        asm volatile("mbarrier.init.shared.b64 [%0], 1;" :: "r"(mb0) : "memory");
        asm volatile("mbarrier.init.shared.b64 [%0], 1;" :: "r"(mb1) : "memory");
    }
    asm volatile("fence.proxy.async.shared::cta;" ::: "memory");
    __syncwarp();

    int pb0 = 0, pb1 = 0;
    int row = warp_steal(l);

    if (row < N_NODES)
        tma_issue(l, buf0, mb0, adj + (size_t)row * N_NODES);

    while (row < N_NODES) {
        int pos = 0;
        int nrow = N_NODES;

        #pragma unroll 1
        for (int s = 0; s < 8; s++) {
            const int b = s & 1;
            // keep the pipe full: issue the NEXT 4KB before processing
            if (s < 7) {
                tma_issue(l, b ? buf0 : buf1, b ? mb0 : mb1,
                          adj + (size_t)row * N_NODES + (s + 1) * 1024);
            } else {
                nrow = warp_steal(l);
                if (nrow < N_NODES)
                    tma_issue(l, b ? buf0 : buf1, b ? mb0 : mb1,
                              adj + (size_t)nrow * N_NODES);
            }
            // wait for the current stage
            if (b == 0) { mbar_wait(mb0, pb0); pb0 ^= 1; }
            else        { mbar_wait(mb1, pb1); pb1 ^= 1; }

            // process 1024 cols from smem
            const uint4* vb = (const uint4*)(dsm + (w * 2 + b) * STAGE_BYTES);
            unsigned mymask = 0u;
            #pragma unroll
            for (int j = 0; j < 8; j++) {
                uint4 v = vb[j * 32 + l];
                unsigned any = v.x | v.y | v.z | v.w;
                if (__ballot_sync(0xFFFFFFFFu, any != 0u)) {
                    #pragma unroll
                    for (int comp = 0; comp < 4; comp++) {
                        unsigned vc = (comp == 0) ? v.x : (comp == 1) ? v.y
                                    : (comp == 2) ? v.z : v.w;
                        unsigned m = __ballot_sync(0xFFFFFFFFu, vc != 0u);
                        if (l == j * 4 + comp) mymask = m;
                    }
                }
            }

            // intra-warp prefix over lane-order mask popcounts
            int cnt = __popc(mymask);
            int p = cnt;
            #pragma unroll
            for (int off = 1; off < 32; off <<= 1) {
                int nb = __shfl_up_sync(0xFFFFFFFFu, p, off);
                if (l >= off) p += nb;
            }
            int excl = p - cnt;
            int wtot = __shfl_sync(0xFFFFFFFFu, p, 31);

            // compact write (deterministic: fixed stage/lane/mask order)
            int wp = pos + excl;
            const int jj = l >> 2, comp = l & 3;
            const int colbase = s * 1024 + jj * 128 + comp;
            unsigned m = mymask;
            while (m) {
                int b2 = __ffs(m) - 1;
                m &= m - 1;
                if (wp < EMAX)
                    g_eidx[row * EMAX + wp] = (unsigned short)(colbase + b2 * 4);
                wp++;
            }
            pos += wtot;
        }

        if (l == 0) g_ecnt[row] = min(pos, EMAX);
        row = nrow;
    }
}

// ========================================================================
// K2: Sall[c] = sum_u Wh[u][c]  (deterministic fixed tree; L2-resident)
// ========================================================================
__global__ __launch_bounds__(256) void k_colsum() {
    const int c = blockIdx.x;
    const int t = threadIdx.x;
    float s = 0.f;
    for (int u = t; u < N_NODES; u += 256)
        s += g_Wh[(size_t)u * F_OUT + c];
    __shared__ float sm[256];
    sm[t] = s;
    __syncthreads();
    #pragma unroll
    for (int off = 128; off; off >>= 1) {
        if (t < off) sm[t] += sm[t + off];
        __syncthreads();
    }
    if (t == 0) g_Sall[c] = sm[0];
}

// ========================================================================
// K3: gather (R9 measured-best) — one warp per row, two edges/iteration.
//   h' = (Sall + sum wt*Wh) / (N + sum wt); ELU; E=0 -> uniform Sall/N.
// ========================================================================
__global__ __launch_bounds__(256) void k_gather(float* __restrict__ out) {
    __shared__ float swt[8][EMAX];
    __shared__ int   sidx[8][EMAX];

    const int t = threadIdx.x;
    const int w = t >> 5, l = t & 31;
    const int u = blockIdx.x * 8 + w;

    const int   E  = g_ecnt[u];
    const float w1 = g_wh1[u];

    float den = 0.f;
    for (int e = l; e < E; e += 32) {
        int idx = (int)g_eidx[u * EMAX + e];
        float ee = w1 + g_wh2[idx];
        ee = (ee >= 0.f) ? ee : ALPHA * ee;
        float wt = __expf(ee) - 1.f;
        swt[w][e]  = wt;
        sidx[w][e] = idx;
        den += wt;
    }
    if (l == 0 && (E & 1)) { swt[w][E] = 0.f; sidx[w][E] = 0; }
    #pragma unroll
    for (int off = 16; off; off >>= 1)
        den += __shfl_xor_sync(0xFFFFFFFFu, den, off);
    __syncwarp();

    const int half  = l >> 4;
    const int cbase = (l & 15) * 4;
    const int E2 = E + (E & 1);
    float4 acc = make_float4(0.f, 0.f, 0.f, 0.f);
    #pragma unroll 4
    for (int e = 0; e < E2; e += 2) {
        int   ei = e + half;
        float wt = swt[w][ei];
        float4 v = *(const float4*)&g_Wh[sidx[w][ei] * F_OUT + cbase];
        acc.x += wt * v.x;
        acc.y += wt * v.y;
        acc.z += wt * v.z;
        acc.w += wt * v.w;
    }

    acc.x += __shfl_down_sync(0xFFFFFFFFu, acc.x, 16);
    acc.y += __shfl_down_sync(0xFFFFFFFFu, acc.y, 16);
    acc.z += __shfl_down_sync(0xFFFFFFFFu, acc.z, 16);
    acc.w += __shfl_down_sync(0xFFFFFFFFu, acc.w, 16);

    if (l < 16) {
        float d = (float)N_NODES + den;
        float4 S = *(const float4*)&g_Sall[cbase];
        float x0 = (S.x + acc.x) / d;
        float x1 = (S.y + acc.y) / d;
        float x2 = (S.z + acc.z) / d;
        float x3 = (S.w + acc.w) / d;
        float4 o;
        o.x = (x0 > 0.f) ? x0 : expm1f(x0);
        o.y = (x1 > 0.f) ? x1 : expm1f(x1);
        o.z = (x2 > 0.f) ? x2 : expm1f(x2);
        o.w = (x3 > 0.f) ? x3 : expm1f(x3);
        *(float4*)&out[(size_t)u * F_OUT + cbase] = o;
    }
}

// ------------------------------------------------------------------------
extern "C" void kernel_launch(void* const* d_in, const int* in_sizes, int n_in,
                              void* d_out, int out_size) {
    const float* h   = (const float*)d_in[0];
    const float* adj = (const float*)d_in[1];
    const float* W   = (const float*)d_in[2];
    const float* a   = (const float*)d_in[3];
    float* out = (float*)d_out;

    cudaFuncSetAttribute(k_fused, cudaFuncAttributeMaxDynamicSharedMemorySize,
                         DSM_BYTES);

    k_init  <<<1, 1>>>();
    k_fused <<<GEMM_BLOCKS + SCAN_BLOCKS, 256, DSM_BYTES>>>(h, W, a, adj);
    k_colsum<<<F_OUT, 256>>>();
    k_gather<<<N_NODES / 8, 256>>>(out);
}

// round 14
// speedup vs baseline: 1.0506x; 1.0506x over previous
#include <cuda_runtime.h>
#include <math.h>

#define N_NODES 8192
#define F_IN    256
#define F_OUT   64
#define ALPHA   0.2f
#define SEG_CAP 32             // per-warp-segment edge cap (mean 4.1, 13-sigma safe)
#define ROWS_PB 8              // rows per scan block
#define GEMM_BLOCKS 256
#define CSUM_BLOCKS 64
#define SALL_BLOCK  (GEMM_BLOCKS + CSUM_BLOCKS)          // 320
#define SCAN_BASE   (SALL_BLOCK + 1)                     // 321
#define SCAN_BLOCKS (N_NODES / ROWS_PB)                  // 1024
#define READY_TARGET (GEMM_BLOCKS + 1)                   // gemm + sall

// Scratch (__device__ globals; no allocation allowed) --------------------
__device__ __align__(16) float g_Wh[N_NODES * F_OUT];   // 2 MB (L2-resident)
__device__ float g_wh1[N_NODES];
__device__ float g_wh2[N_NODES];
__device__ float g_Sall[F_OUT];
__device__ float g_csum_part[CSUM_BLOCKS * F_IN];       // per-block h column sums
__device__ int   g_ready;                               // gemm(256) + sall(1)
__device__ int   g_csum_done;

__global__ void k_init() { g_ready = 0; g_csum_done = 0; }

// ========================================================================
// K_ALL: one kernel, 1345 blocks x 256 threads, <=64 regs.
//  [0,256)    GEMM Wh=h@W (32x64 tile, 2x4 micro) + wh1/wh2; signal ready.
//  [256,320)  csum: partial column sums of h (128 rows each, coalesced).
//  320        Sall = (sum of partials) @ W; signal ready.
//  [321,1345) scan 8 adj rows (warp-independent ballot scan, segments in
//             SMEM); wait ready==257 once; then per-row block gather:
//             wt=exp(lrelu(wh1+wh2))-1, den + channel sums in fixed order,
//             h'=(Sall+sum wt*Wh)/(N+sum wt), ELU. Deterministic: flags
//             gate timing only, every reduction is fixed-order.
// ========================================================================
__global__ __launch_bounds__(256, 4) void k_all(const float* __restrict__ h,
                                                const float* __restrict__ W,
                                                const float* __restrict__ a,
                                                const float* __restrict__ adj,
                                                float* __restrict__ out) {
    // GEMM tiles (gemm branch only)
    __shared__ __align__(16) float hs[32 * 68];     // 8.7 KB
    __shared__ __align__(16) float Ws[64 * 64];     // 16.4 KB
    // scan-gather branch (adds to static smem; total ~34 KB -> occ 4 by regs)
    __shared__ unsigned short eidx_s[ROWS_PB][8][SEG_CAP];  // 4 KB
    __shared__ int   cnt_s[ROWS_PB][8];
    __shared__ __align__(8) float2 sed[8][SEG_CAP];         // 2 KB
    __shared__ float sacc[8][F_OUT];                        // 2 KB
    __shared__ float sden[8];

    const int t = threadIdx.x;
    const int w = t >> 5, l = t & 31;
    const int bid = blockIdx.x;

    if (bid < GEMM_BLOCKS) {
        // ------------------ GEMM branch (R11 measured-best) ------------------
        const int tx = t & 15;
        const int ty = t >> 4;
        const int u0 = bid * 32;

        float acc[2][4] = {};

        for (int kc = 0; kc < 4; kc++) {
            #pragma unroll
            for (int i = 0; i < 2; i++) {
                int idx4 = i * 256 + t;
                int r = idx4 >> 4, k4 = idx4 & 15;
                *(float4*)&hs[r * 68 + k4 * 4] =
                    *(const float4*)&h[(size_t)(u0 + r) * F_IN + kc * 64 + k4 * 4];
            }
            #pragma unroll
            for (int i = 0; i < 4; i++) {
                int idx4 = i * 256 + t;
                int k = idx4 >> 4, c4 = idx4 & 15;
                *(float4*)&Ws[k * 64 + c4 * 4] =
                    *(const float4*)&W[(size_t)(kc * 64 + k) * F_OUT + c4 * 4];
            }
            __syncthreads();

            #pragma unroll
            for (int kk = 0; kk < 64; kk += 4) {
                float4 wv[4], hv[2];
                #pragma unroll
                for (int q = 0; q < 4; q++)
                    wv[q] = *(const float4*)&Ws[(kk + q) * 64 + tx * 4];
                #pragma unroll
                for (int r = 0; r < 2; r++)
                    hv[r] = *(const float4*)&hs[(ty * 2 + r) * 68 + kk];
                #pragma unroll
                for (int r = 0; r < 2; r++) {
                    acc[r][0] += hv[r].x * wv[0].x + hv[r].y * wv[1].x + hv[r].z * wv[2].x + hv[r].w * wv[3].x;
                    acc[r][1] += hv[r].x * wv[0].y + hv[r].y * wv[1].y + hv[r].z * wv[2].y + hv[r].w * wv[3].y;
                    acc[r][2] += hv[r].x * wv[0].z + hv[r].y * wv[1].z + hv[r].z * wv[2].z + hv[r].w * wv[3].z;
                    acc[r][3] += hv[r].x * wv[0].w + hv[r].y * wv[1].w + hv[r].z * wv[2].w + hv[r].w * wv[3].w;
                }
            }
            __syncthreads();
        }

        float4 a1v = *(const float4*)&a[F_OUT + tx * 4];  // source/row term a[f_out:]
        float4 a2v = *(const float4*)&a[tx * 4];          // dest/col  term a[:f_out]
        #pragma unroll
        for (int r = 0; r < 2; r++) {
            int row = u0 + ty * 2 + r;
            *(float4*)&g_Wh[(size_t)row * F_OUT + tx * 4] =
                make_float4(acc[r][0], acc[r][1], acc[r][2], acc[r][3]);
            float s1 = acc[r][0] * a1v.x + acc[r][1] * a1v.y + acc[r][2] * a1v.z + acc[r][3] * a1v.w;
            float s2 = acc[r][0] * a2v.x + acc[r][1] * a2v.y + acc[r][2] * a2v.z + acc[r][3] * a2v.w;
            #pragma unroll
            for (int off = 8; off; off >>= 1) {
                s1 += __shfl_xor_sync(0xFFFFFFFFu, s1, off);
                s2 += __shfl_xor_sync(0xFFFFFFFFu, s2, off);
            }
            if (tx == 0) { g_wh1[row] = s1; g_wh2[row] = s2; }
        }
        __threadfence();
        __syncthreads();
        if (t == 0) atomicAdd(&g_ready, 1);

    } else if (bid < SALL_BLOCK) {
        // ------------------ csum branch: partial col-sums of h --------------
        const int cb = bid - GEMM_BLOCKS;
        const int r0 = cb * (N_NODES / CSUM_BLOCKS);     // 128 rows
        float s = 0.f;
        for (int r = 0; r < N_NODES / CSUM_BLOCKS; r++)
            s += h[(size_t)(r0 + r) * F_IN + t];          // coalesced full rows
        g_csum_part[cb * F_IN + t] = s;
        __threadfence();
        __syncthreads();
        if (t == 0) atomicAdd(&g_csum_done, 1);

    } else if (bid == SALL_BLOCK) {
        // ------------------ Sall = (1^T h) @ W ------------------------------
        if (t == 0) {
            while (atomicAdd(&g_csum_done, 0) < CSUM_BLOCKS) { }
            __threadfence();
        }
        __syncthreads();
        float cs = 0.f;
        #pragma unroll 8
        for (int cb = 0; cb < CSUM_BLOCKS; cb++)          // fixed order
            cs += g_csum_part[cb * F_IN + t];
        // reuse hs smem for csum vector
        hs[t] = cs;
        __syncthreads();
        if (t < F_OUT) {
            float sall = 0.f;
            #pragma unroll 8
            for (int k = 0; k < F_IN; k++)                // fixed order
                sall += hs[k] * W[k * F_OUT + t];
            g_Sall[t] = sall;
        }
        __threadfence();
        __syncthreads();
        if (t == 0) atomicAdd(&g_ready, 1);

    } else {
        // ------------------ scan 8 rows, then gather -------------------------
        const int base = (bid - SCAN_BASE) * ROWS_PB;

        // ---- scan phase: warp-independent, no block syncs ----
        for (int r = 0; r < ROWS_PB; r++) {
            const int row = base + r;
            const uint4* __restrict__ arow = (const uint4*)(adj + (size_t)row * N_NODES);

            uint4 v[8];
            #pragma unroll
            for (int j = 0; j < 8; j++)
                v[j] = __ldcs(&arow[w * 256 + j * 32 + l]);

            unsigned mymask = 0u;
            #pragma unroll
            for (int j = 0; j < 8; j++) {
                unsigned any = v[j].x | v[j].y | v[j].z | v[j].w;
                if (__ballot_sync(0xFFFFFFFFu, any != 0u)) {
                    #pragma unroll
                    for (int comp = 0; comp < 4; comp++) {
                        unsigned vc = (comp == 0) ? v[j].x : (comp == 1) ? v[j].y
                                    : (comp == 2) ? v[j].z : v[j].w;
                        unsigned m = __ballot_sync(0xFFFFFFFFu, vc != 0u);
                        if (l == j * 4 + comp) mymask = m;
                    }
                }
            }

            int cnt = __popc(mymask);
            int p = cnt;
            #pragma unroll
            for (int off = 1; off < 32; off <<= 1) {
                int nb = __shfl_up_sync(0xFFFFFFFFu, p, off);
                if (l >= off) p += nb;
            }
            int excl = p - cnt;
            if (l == 31) cnt_s[r][w] = min(p, SEG_CAP);

            int pos = excl;
            const int jj = l >> 2, comp = l & 3;
            const int colbase = (w * 256 + jj * 32) * 4 + comp;
            unsigned m = mymask;
            while (m) {
                int b = __ffs(m) - 1;
                m &= m - 1;
                if (pos < SEG_CAP)
                    eidx_s[r][w][pos] = (unsigned short)(colbase + b * 4);
                pos++;
            }
        }

        // ---- wait for GEMM + Sall (usually already done) ----
        if (t == 0) {
            while (atomicAdd(&g_ready, 0) < READY_TARGET) { }
            __threadfence();
        }
        __syncthreads();

        // ---- gather phase: per row, block-cooperative ----
        for (int r = 0; r < ROWS_PB; r++) {
            const int row = base + r;
            const int cnt = cnt_s[r][w];
            const float w1 = g_wh1[row];

            float den = 0.f;
            if (l < cnt) {
                int idx = (int)eidx_s[r][w][l];
                float ee = w1 + g_wh2[idx];
                ee = (ee >= 0.f) ? ee : ALPHA * ee;
                float wt = __expf(ee) - 1.f;
                sed[w][l] = make_float2(wt, __int_as_float(idx * F_OUT));
                den = wt;
            }
            #pragma unroll
            for (int off = 16; off; off >>= 1)
                den += __shfl_xor_sync(0xFFFFFFFFu, den, off);
            if (l == 0) sden[w] = den;

            // warp gathers its own segment: 2 channels per lane
            float ax = 0.f, ay = 0.f;
            #pragma unroll 4
            for (int k = 0; k < cnt; k++) {
                float2 ed = sed[w][k];
                const float2 vv = *(const float2*)(g_Wh + __float_as_int(ed.y) + 2 * l);
                ax += ed.x * vv.x;
                ay += ed.x * vv.y;
            }
            sacc[w][2 * l]     = ax;
            sacc[w][2 * l + 1] = ay;
            __syncthreads();

            if (t < F_OUT) {
                float num = g_Sall[t];
                float d   = (float)N_NODES;
                #pragma unroll
                for (int ww = 0; ww < 8; ww++) {          // fixed order
                    num += sacc[ww][t];
                    d   += sden[ww];
                }
                float x = num / d;
                out[(size_t)row * F_OUT + t] = (x > 0.f) ? x : expm1f(x);
            }
            __syncthreads();
        }
    }
}

// ------------------------------------------------------------------------
extern "C" void kernel_launch(void* const* d_in, const int* in_sizes, int n_in,
                              void* d_out, int out_size) {
    const float* h   = (const float*)d_in[0];
    const float* adj = (const float*)d_in[1];
    const float* W   = (const float*)d_in[2];
    const float* a   = (const float*)d_in[3];
    float* out = (float*)d_out;

    k_init<<<1, 1>>>();
    k_all <<<SCAN_BASE + SCAN_BLOCKS, 256>>>(h, W, a, adj, out);
}

// round 15
// speedup vs baseline: 1.2358x; 1.1763x over previous
#include <cuda_runtime.h>
#include <math.h>

#define N_NODES 8192
#define F_IN    256
#define F_OUT   64
#define ALPHA   0.2f
#define SEG_CAP 32             // per-warp-segment edge cap (mean 4.1, 13-sigma safe)
#define ROW_CAP 256            // 8 segments x 32
#define GEMM_BLOCKS 256        // 32-row x 64-col tiles
#define CSUM_BLOCKS 64
#define SALL_BLOCK  (GEMM_BLOCKS + CSUM_BLOCKS)   // 320
#define SCAN_BASE   (SALL_BLOCK + 1)              // 321

// Scratch (__device__ globals; no allocation allowed) --------------------
__device__ __align__(16) float g_Wh[N_NODES * F_OUT];   // 2 MB (L2-resident)
__device__ float g_wh1[N_NODES];
__device__ float g_wh2[N_NODES];
__device__ float g_Sall[F_OUT];
__device__ float g_csum_part[CSUM_BLOCKS * F_IN];
__device__ int   g_csum_done = 0;                       // self-resetting flag
__device__ unsigned char  g_wcnt[N_NODES * 8];          // per-warp-segment counts
__device__ unsigned short g_eidx[N_NODES * ROW_CAP];    // 4 MB, segmented

// ========================================================================
// K1: heterogeneous, 64-reg capped. TWO launches total for the pipeline.
//  [0,256):   GEMM Wh=h@W (32x64 tile, 2x4 micro) + wh1/wh2 epilogue.
//  [256,320): csum partials of h (independent of GEMM; hidden under scan).
//  320:       Sall = (1^T h)@W from partials; resets flag (replay-safe).
//  [321, +8192): scan one adj row; WARP-INDEPENDENT segments (R11
//             measured-best): no __syncthreads, block-churn overlap.
// Deterministic: all reductions fixed-order; flag gates timing only.
// ========================================================================
__global__ __launch_bounds__(256, 4) void k_fused(const float* __restrict__ h,
                                                  const float* __restrict__ W,
                                                  const float* __restrict__ a,
                                                  const float* __restrict__ adj) {
    __shared__ __align__(16) float hs[32 * 68];   // 8.7 KB
    __shared__ __align__(16) float Ws[64 * 64];   // 16.4 KB
    const int t = threadIdx.x;
    const int bid = blockIdx.x;

    if (bid < GEMM_BLOCKS) {
        // ----------------- GEMM branch (2x4 micro, low regs) -----------------
        const int tx = t & 15;
        const int ty = t >> 4;
        const int u0 = bid * 32;

        float acc[2][4] = {};

        for (int kc = 0; kc < 4; kc++) {
            #pragma unroll
            for (int i = 0; i < 2; i++) {
                int idx4 = i * 256 + t;
                int r = idx4 >> 4, k4 = idx4 & 15;
                *(float4*)&hs[r * 68 + k4 * 4] =
                    *(const float4*)&h[(size_t)(u0 + r) * F_IN + kc * 64 + k4 * 4];
            }
            #pragma unroll
            for (int i = 0; i < 4; i++) {
                int idx4 = i * 256 + t;
                int k = idx4 >> 4, c4 = idx4 & 15;
                *(float4*)&Ws[k * 64 + c4 * 4] =
                    *(const float4*)&W[(size_t)(kc * 64 + k) * F_OUT + c4 * 4];
            }
            __syncthreads();

            #pragma unroll
            for (int kk = 0; kk < 64; kk += 4) {
                float4 wv[4], hv[2];
                #pragma unroll
                for (int q = 0; q < 4; q++)
                    wv[q] = *(const float4*)&Ws[(kk + q) * 64 + tx * 4];
                #pragma unroll
                for (int r = 0; r < 2; r++)
                    hv[r] = *(const float4*)&hs[(ty * 2 + r) * 68 + kk];
                #pragma unroll
                for (int r = 0; r < 2; r++) {
                    acc[r][0] += hv[r].x * wv[0].x + hv[r].y * wv[1].x + hv[r].z * wv[2].x + hv[r].w * wv[3].x;
                    acc[r][1] += hv[r].x * wv[0].y + hv[r].y * wv[1].y + hv[r].z * wv[2].y + hv[r].w * wv[3].y;
                    acc[r][2] += hv[r].x * wv[0].z + hv[r].y * wv[1].z + hv[r].z * wv[2].z + hv[r].w * wv[3].z;
                    acc[r][3] += hv[r].x * wv[0].w + hv[r].y * wv[1].w + hv[r].z * wv[2].w + hv[r].w * wv[3].w;
                }
            }
            __syncthreads();
        }

        float4 a1v = *(const float4*)&a[F_OUT + tx * 4];  // source/row term a[f_out:]
        float4 a2v = *(const float4*)&a[tx * 4];          // dest/col  term a[:f_out]
        #pragma unroll
        for (int r = 0; r < 2; r++) {
            int row = u0 + ty * 2 + r;
            *(float4*)&g_Wh[(size_t)row * F_OUT + tx * 4] =
                make_float4(acc[r][0], acc[r][1], acc[r][2], acc[r][3]);
            float s1 = acc[r][0] * a1v.x + acc[r][1] * a1v.y + acc[r][2] * a1v.z + acc[r][3] * a1v.w;
            float s2 = acc[r][0] * a2v.x + acc[r][1] * a2v.y + acc[r][2] * a2v.z + acc[r][3] * a2v.w;
            #pragma unroll
            for (int off = 8; off; off >>= 1) {
                s1 += __shfl_xor_sync(0xFFFFFFFFu, s1, off);
                s2 += __shfl_xor_sync(0xFFFFFFFFu, s2, off);
            }
            if (tx == 0) { g_wh1[row] = s1; g_wh2[row] = s2; }
        }
    } else if (bid < SALL_BLOCK) {
        // --------------- csum branch: partial column sums of h ---------------
        const int cb = bid - GEMM_BLOCKS;
        const int r0 = cb * (N_NODES / CSUM_BLOCKS);     // 128 rows each
        float s = 0.f;
        #pragma unroll 4
        for (int r = 0; r < N_NODES / CSUM_BLOCKS; r++)
            s += h[(size_t)(r0 + r) * F_IN + t];          // coalesced
        g_csum_part[cb * F_IN + t] = s;
        __threadfence();
        __syncthreads();
        if (t == 0) atomicAdd(&g_csum_done, 1);
    } else if (bid == SALL_BLOCK) {
        // --------------- Sall = (1^T h) @ W ----------------------------------
        if (t == 0) {
            while (atomicAdd(&g_csum_done, 0) < CSUM_BLOCKS) { }
            __threadfence();
        }
        __syncthreads();
        float cs = 0.f;
        #pragma unroll 8
        for (int cb = 0; cb < CSUM_BLOCKS; cb++)          // fixed order
            cs += g_csum_part[cb * F_IN + t];
        hs[t] = cs;
        __syncthreads();
        if (t == 0) g_csum_done = 0;                      // replay-safe reset
        if (t < F_OUT) {
            float sall = 0.f;
            #pragma unroll 8
            for (int k = 0; k < F_IN; k++)                // fixed order
                sall += hs[k] * W[k * F_OUT + t];
            g_Sall[t] = sall;
        }
    } else {
        // ------------- scan branch: warp-independent segments (R11) ---------
        const int row = bid - SCAN_BASE;
        const int w = t >> 5, l = t & 31;
        const uint4* __restrict__ arow = (const uint4*)(adj + (size_t)row * N_NODES);

        uint4 v[8];
        #pragma unroll
        for (int j = 0; j < 8; j++)
            v[j] = __ldcs(&arow[w * 256 + j * 32 + l]);

        unsigned mymask = 0u;
        #pragma unroll
        for (int j = 0; j < 8; j++) {
            unsigned any = v[j].x | v[j].y | v[j].z | v[j].w;
            if (__ballot_sync(0xFFFFFFFFu, any != 0u)) {
                #pragma unroll
                for (int comp = 0; comp < 4; comp++) {
                    unsigned vc = (comp == 0) ? v[j].x : (comp == 1) ? v[j].y
                                : (comp == 2) ? v[j].z : v[j].w;
                    unsigned m = __ballot_sync(0xFFFFFFFFu, vc != 0u);
                    if (l == j * 4 + comp) mymask = m;
                }
            }
        }

        int cnt = __popc(mymask);
        int p = cnt;
        #pragma unroll
        for (int off = 1; off < 32; off <<= 1) {
            int nb = __shfl_up_sync(0xFFFFFFFFu, p, off);
            if (l >= off) p += nb;
        }
        int excl = p - cnt;
        if (l == 31) g_wcnt[row * 8 + w] = (unsigned char)min(p, SEG_CAP);

        int pos = excl;
        const int j = l >> 2, comp = l & 3;
        const int colbase = (w * 256 + j * 32) * 4 + comp;
        unsigned m = mymask;
        while (m) {
            int b = __ffs(m) - 1;
            m &= m - 1;
            if (pos < SEG_CAP)
                g_eidx[row * ROW_CAP + w * SEG_CAP + pos] =
                    (unsigned short)(colbase + b * 4);
            pos++;
        }
    }
}

// ========================================================================
// K2: gather — one warp per row, NO local-memory (shift-trick offsets).
//   counts: one u64 load; per-lane segment count/offset/E via byte-sum
//   multiply trick (pure register shifts — no indexed arrays, no LDL).
//   phase 1: lane l -> segment l>>2, slots (l&3)+4k (all lanes active);
//   compact position off(seg)+k; (wt, Wh-offset) packed into float2 smem.
//   den per-lane fixed order + xor-tree. phase 2: 2 edges/iter, 4
//   channels/lane (LDS64+LDG128+4 FFMA), cross-half shfl-down combine.
//   h' = (Sall + sum wt*Wh) / (N + sum wt); ELU; E=0 -> uniform Sall/N.
// ========================================================================
__global__ __launch_bounds__(256) void k_gather(float* __restrict__ out) {
    __shared__ __align__(8) float2 sed[8][ROW_CAP];   // 16 KB

    const int t = threadIdx.x;
    const int w = t >> 5, l = t & 31;
    const int u = blockIdx.x * 8 + w;

    const unsigned long long c = *(const unsigned long long*)&g_wcnt[u * 8];
    const int seg = l >> 2, k0 = l & 3;
    const int scnt = (int)((c >> (seg * 8)) & 0xFFULL);
    const unsigned long long lowm = c & ((1ULL << (seg * 8)) - 1ULL);
    const int soff = (int)((lowm * 0x0101010101010101ULL) >> 56);
    const int E    = (int)((c    * 0x0101010101010101ULL) >> 56);

    const float w1 = g_wh1[u];

    // phase 1: all lanes active; no communication for positions
    float den = 0.f;
    for (int k = k0; k < scnt; k += 4) {
        int idx = (int)g_eidx[u * ROW_CAP + seg * SEG_CAP + k];
        float ee = w1 + g_wh2[idx];
        ee = (ee >= 0.f) ? ee : ALPHA * ee;
        float wt = __expf(ee) - 1.f;
        sed[w][soff + k] = make_float2(wt, __int_as_float(idx * F_OUT));
        den += wt;
    }
    if (l == 0 && (E & 1)) sed[w][E] = make_float2(0.f, __int_as_float(0));
    #pragma unroll
    for (int o = 16; o; o >>= 1)
        den += __shfl_xor_sync(0xFFFFFFFFu, den, o);
    __syncwarp();

    // phase 2: 2 edges/iteration, 4 channels per lane
    const int half  = l >> 4;
    const int cbase = (l & 15) * 4;
    const int E2 = E + (E & 1);
    float4 acc = make_float4(0.f, 0.f, 0.f, 0.f);
    #pragma unroll 4
    for (int e = 0; e < E2; e += 2) {
        float2 ed = sed[w][e + half];
        float4 v  = *(const float4*)(g_Wh + __float_as_int(ed.y) + cbase);
        acc.x += ed.x * v.x;
        acc.y += ed.x * v.y;
        acc.z += ed.x * v.z;
        acc.w += ed.x * v.w;
    }

    acc.x += __shfl_down_sync(0xFFFFFFFFu, acc.x, 16);
    acc.y += __shfl_down_sync(0xFFFFFFFFu, acc.y, 16);
    acc.z += __shfl_down_sync(0xFFFFFFFFu, acc.z, 16);
    acc.w += __shfl_down_sync(0xFFFFFFFFu, acc.w, 16);

    if (l < 16) {
        float d = (float)N_NODES + den;
        float4 S = *(const float4*)&g_Sall[cbase];
        float x0 = (S.x + acc.x) / d;
        float x1 = (S.y + acc.y) / d;
        float x2 = (S.z + acc.z) / d;
        float x3 = (S.w + acc.w) / d;
        float4 o;
        o.x = (x0 > 0.f) ? x0 : expm1f(x0);
        o.y = (x1 > 0.f) ? x1 : expm1f(x1);
        o.z = (x2 > 0.f) ? x2 : expm1f(x2);
        o.w = (x3 > 0.f) ? x3 : expm1f(x3);
        *(float4*)&out[(size_t)u * F_OUT + cbase] = o;
    }
}

// ------------------------------------------------------------------------
extern "C" void kernel_launch(void* const* d_in, const int* in_sizes, int n_in,
                              void* d_out, int out_size) {
    const float* h   = (const float*)d_in[0];
    const float* adj = (const float*)d_in[1];
    const float* W   = (const float*)d_in[2];
    const float* a   = (const float*)d_in[3];
    float* out = (float*)d_out;

    k_fused <<<SCAN_BASE + N_NODES, 256>>>(h, W, a, adj);
    k_gather<<<N_NODES / 8, 256>>>(out);
}